// round 13
// baseline (speedup 1.0000x reference)
#include <cuda_runtime.h>
#include <math.h>
#include <stdint.h>

#define SUBNETS 64
#define NH1 10
#define NH2 6
#define GRIDN 101
#define K_INT 52             // intervals (delta = 1/4)
#define KNOTS 53             // knots = K_INT + 1
#define TAB_LO  (-6.5f)
#define TAB_DX  (0.25f)      // 1/4
#define TAB_INVDX (4.0f)
#define TAB_BIAS  (26.0f)    // 6.5 * 4

#define EVAL_BLOCK 1024
#define EVAL_GRID  296       // 2 blocks per SM (148 SMs)
#define TAB_FLOATS (K_INT * SUBNETS * 4)        // 13312 floats = 53,248 B
#define TILE_ELEMS 4096                         // 16 KB per tile
#define SMEM_FLOATS (TAB_FLOATS + 2 * TILE_ELEMS)
#define SMEM_BYTES  (SMEM_FLOATS * (int)sizeof(float))   // 86,016 B

// Piecewise-cubic table, INTERVAL-MAJOR: g_table[j*64 + s] = (c0,c1,c2,c3).
// Conflict-free warp LDS.128 gathers: bank-quad = (j*64+s) mod 8 = s mod 8,
// s = tid & 63 is 8 consecutive values per 8-lane phase.
__device__ float4 g_table[K_INT * SUBNETS];

__device__ __forceinline__ void cp_async16(uint32_t smem_addr, const void* gptr) {
    asm volatile("cp.async.cg.shared.global [%0], [%1], 16;"
                 :: "r"(smem_addr), "l"(gptr) : "memory");
}
__device__ __forceinline__ void cp_commit() {
    asm volatile("cp.async.commit_group;" ::: "memory");
}
template <int N>
__device__ __forceinline__ void cp_wait() {
    asm volatile("cp.async.wait_group %0;" :: "n"(N) : "memory");
}

// Accurate MLP evaluation (value + analytic derivative) for one subnet.
__device__ __forceinline__ void mlp_eval(
    float x, int s,
    const float* __restrict__ W1, const float* __restrict__ b1,
    const float* __restrict__ W2, const float* __restrict__ b2,
    const float* __restrict__ W3, const float* __restrict__ b3,
    float* f_out, float* d_out)
{
    float h1[NH1], dh1[NH1];
#pragma unroll
    for (int h = 0; h < NH1; h++) {
        float w = W1[s * NH1 + h];
        float p = fmaf(w, x, b1[s * NH1 + h]);
        float t = tanhf(p);
        h1[h]  = t;
        dh1[h] = (1.0f - t * t) * w;
    }
    float f = b3[s];
    float d = 0.0f;
#pragma unroll
    for (int k = 0; k < NH2; k++) {
        float a  = b2[s * NH2 + k];
        float da = 0.0f;
#pragma unroll
        for (int h = 0; h < NH1; h++) {
            float w2 = W2[(s * NH1 + h) * NH2 + k];
            a  = fmaf(h1[h],  w2, a);
            da = fmaf(dh1[h], w2, da);
        }
        float t  = tanhf(a);
        float w3 = W3[s * NH2 + k];
        f = fmaf(t, w3, f);
        d = fmaf((1.0f - t * t) * da, w3, d);
    }
    *f_out = f;
    *d_out = d;
}

// One block per subnet: grid stats + Hermite coefficients (normalization
// pre-folded); writes transposed (interval-major) table.
__global__ __launch_bounds__(256)
void setup_kernel(const float* __restrict__ W1, const float* __restrict__ b1,
                  const float* __restrict__ W2, const float* __restrict__ b2,
                  const float* __restrict__ W3, const float* __restrict__ b3)
{
    __shared__ float sh_g[GRIDN];
    __shared__ float sh_f[KNOTS];
    __shared__ float sh_d[KNOTS];
    __shared__ float sh_mean, sh_inv;

    const int s = blockIdx.x;
    const int t = threadIdx.x;

    if (t < GRIDN) {
        float x = fmaf((float)t, 0.02f, -1.0f);   // linspace(-1,1,101)
        float f, d;
        mlp_eval(x, s, W1, b1, W2, b2, W3, b3, &f, &d);
        sh_g[t] = f;
    }
    if (t < KNOTS) {
        float x = fmaf((float)t, TAB_DX, TAB_LO);
        float f, d;
        mlp_eval(x, s, W1, b1, W2, b2, W3, b3, &f, &d);
        sh_f[t] = f;
        sh_d[t] = d;
    }
    __syncthreads();

    if (t < 32) {
        double m = 0.0, m2 = 0.0;
        for (int i = t; i < GRIDN; i += 32) {
            double g = (double)sh_g[i];
            m  += g;
            m2 += g * g;
        }
#pragma unroll
        for (int o = 16; o > 0; o >>= 1) {
            m  += __shfl_down_sync(0xFFFFFFFFu, m,  o);
            m2 += __shfl_down_sync(0xFFFFFFFFu, m2, o);
        }
        if (t == 0) {
            m  /= (double)GRIDN;
            m2 /= (double)GRIDN;
            double var = m2 - m * m;
            if (var < 0.0) var = 0.0;
            double sd = sqrt(var);
            if (sd < 1e-10) sd = 1e-10;
            sh_mean = (float)m;
            sh_inv  = (float)(1.0 / sd);
        }
    }
    __syncthreads();

    if (t < K_INT) {
        const float mean = sh_mean;
        const float inv  = sh_inv;
        float f0 = (sh_f[t]     - mean) * inv;
        float f1 = (sh_f[t + 1] - mean) * inv;
        float m0 = sh_d[t]     * inv * TAB_DX;
        float m1 = sh_d[t + 1] * inv * TAB_DX;
        float c2 = 3.0f * (f1 - f0) - 2.0f * m0 - m1;
        float c3 = 2.0f * (f0 - f1) + m0 + m1;
        g_table[t * SUBNETS + s] = make_float4(f0, m0, c2, c3);
    }
}

__device__ __forceinline__ float cubic_lookup(const float4* __restrict__ tab,
                                              int s, float x)
{
    float q  = fmaf(x, TAB_INVDX, TAB_BIAS);   // (x + 6.5) * 4
    float jf = floorf(q);
    jf = fminf(fmaxf(jf, 0.0f), (float)(K_INT - 1));
    float tt = q - jf;
    float4 c = tab[(int)jf * SUBNETS + s];
    return fmaf(fmaf(fmaf(c.w, tt, c.z), tt, c.y), tt, c.x);
}

// Main kernel: cp.async double-buffered input staging.
// Blocks own contiguous 4096-element tiles; each thread DMAs 16B/tile into
// smem while the previous tile is computed. The per-warp critical path is
// LDS-only (no long-scoreboard global waits). Subnet id stays s = tid & 63
// for every tile element (4096 and 1024 are multiples of 64).
__global__ __launch_bounds__(EVAL_BLOCK, 2)
void eval_kernel(const float* __restrict__ in, const int* __restrict__ idx,
                 float* __restrict__ out, int n)
{
    extern __shared__ float smem[];
    float4* tab = reinterpret_cast<float4*>(smem);       // [K_INT*SUBNETS]
    float*  xb0 = smem + TAB_FLOATS;
    float*  xb1 = smem + TAB_FLOATS + TILE_ELEMS;

    const float4* gt = g_table;
    for (int i = threadIdx.x; i < K_INT * SUBNETS; i += EVAL_BLOCK)
        tab[i] = gt[i];

    const int t0 = threadIdx.x;
    const int s  = t0 & 63;

    // Block-uniform identity check (branch encloses __syncthreads).
    bool identity = true;
    for (int k = 0; k < SUBNETS; k++)
        identity &= (__ldg(idx + k) == k);

    __syncthreads();   // table staged

    if (identity) {
        const int ntiles = n >> 12;                     // full 4096-elem tiles
        uint32_t sb0 = (uint32_t)__cvta_generic_to_shared(xb0) + t0 * 16;
        uint32_t sb1 = (uint32_t)__cvta_generic_to_shared(xb1) + t0 * 16;

        int t = blockIdx.x;
        int buf = 0;
        if (t < ntiles) {
            cp_async16(sb0, in + (t << 12) + t0 * 4);
            cp_commit();
        }
        while (t < ntiles) {
            const int tn = t + EVAL_GRID;
            if (tn < ntiles) {
                cp_async16(buf ? sb0 : sb1, in + (tn << 12) + t0 * 4);
                cp_commit();
                cp_wait<1>();          // previous tile's group drained
            } else {
                cp_wait<0>();
            }
            __syncthreads();           // all threads' copies visible

            const float* xb = buf ? xb1 : xb0;
            const int gbase = (t << 12) + t0;
#pragma unroll
            for (int j = 0; j < 4; j++) {
                float x = xb[t0 + j * 1024];
                out[gbase + j * 1024] = cubic_lookup(tab, s, x);
            }
            __syncthreads();           // done reading before buffer reuse
            t = tn;
            buf ^= 1;
        }

        // Remainder elements (n not multiple of 4096): grid-stride scalar.
        const int rem_base = ntiles << 12;
        for (int i = rem_base + blockIdx.x * EVAL_BLOCK + t0; i < n;
             i += EVAL_GRID * EVAL_BLOCK)
            out[i] = cubic_lookup(tab, s, __ldg(in + i));
    } else {
        // Generic-idx fallback: round-6 global path (no barriers inside).
        const int tid      = blockIdx.x * EVAL_BLOCK + t0;
        const int nthreads = EVAL_GRID * EVAL_BLOCK;
        const int off      = __ldg(idx + s) - s;
        const float* __restrict__ inp = in + off;

        int i = tid;
        for (; i + 3 * nthreads < n; i += 4 * nthreads) {
            float x0 = __ldg(inp + i);
            float x1 = __ldg(inp + i +     nthreads);
            float x2 = __ldg(inp + i + 2 * nthreads);
            float x3 = __ldg(inp + i + 3 * nthreads);
            out[i]                = cubic_lookup(tab, s, x0);
            out[i +     nthreads] = cubic_lookup(tab, s, x1);
            out[i + 2 * nthreads] = cubic_lookup(tab, s, x2);
            out[i + 3 * nthreads] = cubic_lookup(tab, s, x3);
        }
        for (; i < n; i += nthreads)
            out[i] = cubic_lookup(tab, s, __ldg(inp + i));
    }
}

extern "C" void kernel_launch(void* const* d_in, const int* in_sizes, int n_in,
                              void* d_out, int out_size)
{
    const float* inputs = (const float*)d_in[0];
    const int*   idx    = (const int*)  d_in[1];
    const float* W1     = (const float*)d_in[2];
    const float* b1     = (const float*)d_in[3];
    const float* W2     = (const float*)d_in[4];
    const float* b2     = (const float*)d_in[5];
    const float* W3     = (const float*)d_in[6];
    const float* b3     = (const float*)d_in[7];
    float*       outp   = (float*)d_out;

    cudaFuncSetAttribute(eval_kernel,
                         cudaFuncAttributeMaxDynamicSharedMemorySize,
                         SMEM_BYTES);

    setup_kernel<<<SUBNETS, 256>>>(W1, b1, W2, b2, W3, b3);

    eval_kernel<<<EVAL_GRID, EVAL_BLOCK, SMEM_BYTES>>>(inputs, idx, outp,
                                                       out_size);
}

// round 14
// speedup vs baseline: 1.1369x; 1.1369x over previous
#include <cuda_runtime.h>
#include <math.h>

#define SUBNETS 64
#define NH1 10
#define NH2 6
#define GRIDN 101
#define K_INT 52             // intervals (delta = 1/4)
#define KNOTS 53             // knots = K_INT + 1
#define TAB_LO  (-6.5f)
#define TAB_DX  (0.25f)      // 1/4
#define TAB_INVDX (4.0f)
#define TAB_BIAS  (26.0f)    // 6.5 * 4

#define EVAL_BLOCK 1024
#define EVAL_GRID  296       // 2 blocks per SM (148 SMs)
#define SMEM_BYTES (SUBNETS * K_INT * (int)sizeof(float4))  // 53,248 B

// Piecewise-cubic table, INTERVAL-MAJOR: g_table[j*64 + s] = (c0,c1,c2,c3)
// for subnet s, interval j. Conflict-free warp LDS.128 gathers: within an
// 8-lane phase, bank-quad = (j*64+s) mod 8 = s mod 8, and s = tid & 63 is
// 8 consecutive values per phase.
__device__ float4 g_table[K_INT * SUBNETS];

__device__ __forceinline__ void prefetch_l2(const void* p) {
    asm volatile("prefetch.global.L2 [%0];" :: "l"(p));
}

// Accurate MLP evaluation (value + analytic derivative) for one subnet.
__device__ __forceinline__ void mlp_eval(
    float x, int s,
    const float* __restrict__ W1, const float* __restrict__ b1,
    const float* __restrict__ W2, const float* __restrict__ b2,
    const float* __restrict__ W3, const float* __restrict__ b3,
    float* f_out, float* d_out)
{
    float h1[NH1], dh1[NH1];
#pragma unroll
    for (int h = 0; h < NH1; h++) {
        float w = W1[s * NH1 + h];
        float p = fmaf(w, x, b1[s * NH1 + h]);
        float t = tanhf(p);
        h1[h]  = t;
        dh1[h] = (1.0f - t * t) * w;
    }
    float f = b3[s];
    float d = 0.0f;
#pragma unroll
    for (int k = 0; k < NH2; k++) {
        float a  = b2[s * NH2 + k];
        float da = 0.0f;
#pragma unroll
        for (int h = 0; h < NH1; h++) {
            float w2 = W2[(s * NH1 + h) * NH2 + k];
            a  = fmaf(h1[h],  w2, a);
            da = fmaf(dh1[h], w2, da);
        }
        float t  = tanhf(a);
        float w3 = W3[s * NH2 + k];
        f = fmaf(t, w3, f);
        d = fmaf((1.0f - t * t) * da, w3, d);
    }
    *f_out = f;
    *d_out = d;
}

// One block per subnet: grid stats (parallel double reduction) + Hermite
// coefficients with normalization folded in; writes transposed table.
__global__ __launch_bounds__(256)
void setup_kernel(const float* __restrict__ W1, const float* __restrict__ b1,
                  const float* __restrict__ W2, const float* __restrict__ b2,
                  const float* __restrict__ W3, const float* __restrict__ b3)
{
    __shared__ float sh_g[GRIDN];
    __shared__ float sh_f[KNOTS];
    __shared__ float sh_d[KNOTS];
    __shared__ float sh_mean, sh_inv;

    const int s = blockIdx.x;
    const int t = threadIdx.x;

    if (t < GRIDN) {
        float x = fmaf((float)t, 0.02f, -1.0f);   // linspace(-1,1,101)
        float f, d;
        mlp_eval(x, s, W1, b1, W2, b2, W3, b3, &f, &d);
        sh_g[t] = f;
    }
    if (t < KNOTS) {
        float x = fmaf((float)t, TAB_DX, TAB_LO);
        float f, d;
        mlp_eval(x, s, W1, b1, W2, b2, W3, b3, &f, &d);
        sh_f[t] = f;
        sh_d[t] = d;
    }
    __syncthreads();

    // Warp 0: parallel double-precision sum / sumsq over the 101 grid values.
    if (t < 32) {
        double m = 0.0, m2 = 0.0;
        for (int i = t; i < GRIDN; i += 32) {
            double g = (double)sh_g[i];
            m  += g;
            m2 += g * g;
        }
#pragma unroll
        for (int o = 16; o > 0; o >>= 1) {
            m  += __shfl_down_sync(0xFFFFFFFFu, m,  o);
            m2 += __shfl_down_sync(0xFFFFFFFFu, m2, o);
        }
        if (t == 0) {
            m  /= (double)GRIDN;
            m2 /= (double)GRIDN;
            double var = m2 - m * m;
            if (var < 0.0) var = 0.0;
            double sd = sqrt(var);
            if (sd < 1e-10) sd = 1e-10;
            sh_mean = (float)m;
            sh_inv  = (float)(1.0 / sd);
        }
    }
    __syncthreads();

    if (t < K_INT) {
        const float mean = sh_mean;
        const float inv  = sh_inv;
        float f0 = (sh_f[t]     - mean) * inv;
        float f1 = (sh_f[t + 1] - mean) * inv;
        float m0 = sh_d[t]     * inv * TAB_DX;
        float m1 = sh_d[t + 1] * inv * TAB_DX;
        float c2 = 3.0f * (f1 - f0) - 2.0f * m0 - m1;
        float c3 = 2.0f * (f0 - f1) + m0 + m1;
        g_table[t * SUBNETS + s] = make_float4(f0, m0, c2, c3);  // transposed
    }
}

__device__ __forceinline__ float cubic_lookup(const float4* __restrict__ tab,
                                              int s, float x)
{
    float q  = fmaf(x, TAB_INVDX, TAB_BIAS);   // (x + 6.5) * 4
    float jf = floorf(q);
    jf = fminf(fmaxf(jf, 0.0f), (float)(K_INT - 1));
    float tt = q - jf;
    float4 c = tab[(int)jf * SUBNETS + s];
    return fmaf(fmaf(fmaf(c.w, tt, c.z), tt, c.y), tt, c.x);
}

// Main kernel (round-6 champion + L2 software prefetch):
// one subnet per thread (s = tid & 63), coalesced LDG.32/STG.32,
// conflict-free LDS.128 table gathers, plain unroll x4, 64 warps/SM.
// Each iteration prefetches the NEXT iteration's 4 input lines into L2
// (prefetch.global.L2: no registers, no scoreboard). Demand loads then hit
// L2 (~250 cyc) instead of queued DRAM, and the prefetch stream keeps HBM
// continuously busy instead of burst-and-wait.
__global__ __launch_bounds__(EVAL_BLOCK, 2)
void eval_kernel(const float* __restrict__ in, const int* __restrict__ idx,
                 float* __restrict__ out, int n)
{
    extern __shared__ float4 tab[];          // [K_INT][SUBNETS]

    for (int i = threadIdx.x; i < K_INT * SUBNETS; i += EVAL_BLOCK)
        tab[i] = g_table[i];
    __syncthreads();

    const int tid      = blockIdx.x * EVAL_BLOCK + threadIdx.x;
    const int nthreads = EVAL_GRID * EVAL_BLOCK;     // multiple of 64

    const int s   = tid & 63;
    const int off = idx[s] - s;   // in[b*64 + idx[s]] == in[i + off]
    const float* __restrict__ inp = in + off;

    int i = tid;
    for (; i + 3 * nthreads < n; i += 4 * nthreads) {
        // Prefetch next iteration's lines into L2 (guarded, non-faulting by
        // construction: addresses stay inside the input buffer).
        const int ip = i + 4 * nthreads;
        if (ip + 3 * nthreads < n) {
            prefetch_l2(inp + ip);
            prefetch_l2(inp + ip +     nthreads);
            prefetch_l2(inp + ip + 2 * nthreads);
            prefetch_l2(inp + ip + 3 * nthreads);
        }

        float x0 = __ldg(inp + i);
        float x1 = __ldg(inp + i +     nthreads);
        float x2 = __ldg(inp + i + 2 * nthreads);
        float x3 = __ldg(inp + i + 3 * nthreads);
        float r0 = cubic_lookup(tab, s, x0);
        float r1 = cubic_lookup(tab, s, x1);
        float r2 = cubic_lookup(tab, s, x2);
        float r3 = cubic_lookup(tab, s, x3);
        out[i]                = r0;
        out[i +     nthreads] = r1;
        out[i + 2 * nthreads] = r2;
        out[i + 3 * nthreads] = r3;
    }
    for (; i < n; i += nthreads) {
        float x = __ldg(inp + i);
        out[i] = cubic_lookup(tab, s, x);
    }
}

extern "C" void kernel_launch(void* const* d_in, const int* in_sizes, int n_in,
                              void* d_out, int out_size)
{
    const float* inputs = (const float*)d_in[0];
    const int*   idx    = (const int*)  d_in[1];
    const float* W1     = (const float*)d_in[2];
    const float* b1     = (const float*)d_in[3];
    const float* W2     = (const float*)d_in[4];
    const float* b2     = (const float*)d_in[5];
    const float* W3     = (const float*)d_in[6];
    const float* b3     = (const float*)d_in[7];
    float*       outp   = (float*)d_out;

    cudaFuncSetAttribute(eval_kernel,
                         cudaFuncAttributeMaxDynamicSharedMemorySize,
                         SMEM_BYTES);

    setup_kernel<<<SUBNETS, 256>>>(W1, b1, W2, b2, W3, b3);

    eval_kernel<<<EVAL_GRID, EVAL_BLOCK, SMEM_BYTES>>>(inputs, idx, outp,
                                                       out_size);
}

// round 15
// speedup vs baseline: 1.2354x; 1.0866x over previous
#include <cuda_runtime.h>
#include <math.h>

#define SUBNETS 64
#define NH1 10
#define NH2 6
#define GRIDN 101
#define K_INT 52             // intervals (delta = 1/4)
#define KNOTS 53             // knots = K_INT + 1
#define TAB_LO  (-6.5f)
#define TAB_DX  (0.25f)      // 1/4
#define TAB_INVDX (4.0f)
#define TAB_BIAS  (26.0f)    // 6.5 * 4

#define EVAL_BLOCK 1024
#define EVAL_GRID  296       // 2 blocks per SM (148 SMs)
#define SMEM_BYTES (SUBNETS * K_INT * (int)sizeof(float4))  // 53,248 B

// Piecewise-cubic table, INTERVAL-MAJOR with PERMUTED subnet columns:
// g_table[j*64 + P(s)], P(s) = ((s&3)<<4) | (s>>2).
// Thread t owns subnets s_u = (4t+u)&63 (float4 I/O); its lookup column is
// P(s_u) = (t&15) + 16u. Within any 8-lane LDS.128 phase the bank-quad index
// is ((t&15)+16u) mod 8 = t mod 8 -> all 8 distinct, for ANY data-dependent
// interval j. Conflict-free gathers AND vectorized 128-bit global I/O.
__device__ float4 g_table[K_INT * SUBNETS];

// Accurate MLP evaluation (value + analytic derivative) for one subnet.
__device__ __forceinline__ void mlp_eval(
    float x, int s,
    const float* __restrict__ W1, const float* __restrict__ b1,
    const float* __restrict__ W2, const float* __restrict__ b2,
    const float* __restrict__ W3, const float* __restrict__ b3,
    float* f_out, float* d_out)
{
    float h1[NH1], dh1[NH1];
#pragma unroll
    for (int h = 0; h < NH1; h++) {
        float w = W1[s * NH1 + h];
        float p = fmaf(w, x, b1[s * NH1 + h]);
        float t = tanhf(p);
        h1[h]  = t;
        dh1[h] = (1.0f - t * t) * w;
    }
    float f = b3[s];
    float d = 0.0f;
#pragma unroll
    for (int k = 0; k < NH2; k++) {
        float a  = b2[s * NH2 + k];
        float da = 0.0f;
#pragma unroll
        for (int h = 0; h < NH1; h++) {
            float w2 = W2[(s * NH1 + h) * NH2 + k];
            a  = fmaf(h1[h],  w2, a);
            da = fmaf(dh1[h], w2, da);
        }
        float t  = tanhf(a);
        float w3 = W3[s * NH2 + k];
        f = fmaf(t, w3, f);
        d = fmaf((1.0f - t * t) * da, w3, d);
    }
    *f_out = f;
    *d_out = d;
}

// One block per subnet: grid stats (parallel double reduction) + Hermite
// coefficients with normalization folded in; writes permuted-column table.
__global__ __launch_bounds__(256)
void setup_kernel(const float* __restrict__ W1, const float* __restrict__ b1,
                  const float* __restrict__ W2, const float* __restrict__ b2,
                  const float* __restrict__ W3, const float* __restrict__ b3)
{
    __shared__ float sh_g[GRIDN];
    __shared__ float sh_f[KNOTS];
    __shared__ float sh_d[KNOTS];
    __shared__ float sh_mean, sh_inv;

    const int s = blockIdx.x;
    const int t = threadIdx.x;

    if (t < GRIDN) {
        float x = fmaf((float)t, 0.02f, -1.0f);   // linspace(-1,1,101)
        float f, d;
        mlp_eval(x, s, W1, b1, W2, b2, W3, b3, &f, &d);
        sh_g[t] = f;
    }
    if (t < KNOTS) {
        float x = fmaf((float)t, TAB_DX, TAB_LO);
        float f, d;
        mlp_eval(x, s, W1, b1, W2, b2, W3, b3, &f, &d);
        sh_f[t] = f;
        sh_d[t] = d;
    }
    __syncthreads();

    // Warp 0: parallel double-precision sum / sumsq over the 101 grid values.
    if (t < 32) {
        double m = 0.0, m2 = 0.0;
        for (int i = t; i < GRIDN; i += 32) {
            double g = (double)sh_g[i];
            m  += g;
            m2 += g * g;
        }
#pragma unroll
        for (int o = 16; o > 0; o >>= 1) {
            m  += __shfl_down_sync(0xFFFFFFFFu, m,  o);
            m2 += __shfl_down_sync(0xFFFFFFFFu, m2, o);
        }
        if (t == 0) {
            m  /= (double)GRIDN;
            m2 /= (double)GRIDN;
            double var = m2 - m * m;
            if (var < 0.0) var = 0.0;
            double sd = sqrt(var);
            if (sd < 1e-10) sd = 1e-10;
            sh_mean = (float)m;
            sh_inv  = (float)(1.0 / sd);
        }
    }
    __syncthreads();

    if (t < K_INT) {
        const float mean = sh_mean;
        const float inv  = sh_inv;
        float f0 = (sh_f[t]     - mean) * inv;
        float f1 = (sh_f[t + 1] - mean) * inv;
        float m0 = sh_d[t]     * inv * TAB_DX;
        float m1 = sh_d[t + 1] * inv * TAB_DX;
        float c2 = 3.0f * (f1 - f0) - 2.0f * m0 - m1;
        float c3 = 2.0f * (f0 - f1) + m0 + m1;
        const int perm = ((s & 3) << 4) | (s >> 2);      // P(s)
        g_table[t * SUBNETS + perm] = make_float4(f0, m0, c2, c3);
    }
}

__device__ __forceinline__ float cubic_lookup(const float4* __restrict__ tab,
                                              int col, float x)
{
    float q  = fmaf(x, TAB_INVDX, TAB_BIAS);   // (x + 6.5) * 4
    float jf = floorf(q);
    jf = fminf(fmaxf(jf, 0.0f), (float)(K_INT - 1));
    float tt = q - jf;
    float4 c = tab[(int)jf * SUBNETS + col];
    return fmaf(fmaf(fmaf(c.w, tt, c.z), tt, c.y), tt, c.x);
}

// Main kernel: float4 global I/O (1 LDG.128 + 1 STG.128 per 4 elements)
// with conflict-free permuted-column LDS.128 table gathers.
// LSU cycles per 128 elements: ~30 vs ~43 for the scalar version.
__global__ __launch_bounds__(EVAL_BLOCK, 2)
void eval_kernel(const float* __restrict__ in, const int* __restrict__ idx,
                 float* __restrict__ out, int n4)
{
    extern __shared__ float4 tab[];          // [K_INT][SUBNETS], permuted cols

    for (int i = threadIdx.x; i < K_INT * SUBNETS; i += EVAL_BLOCK)
        tab[i] = g_table[i];
    __syncthreads();

    const int tid      = blockIdx.x * EVAL_BLOCK + threadIdx.x;
    const int nthreads = EVAL_GRID * EVAL_BLOCK;   // multiple of 16

    // Per-thread subnets: s_u = (4*tid + u) & 63 (loop-invariant: stride
    // 4*nthreads is a multiple of 64). Lookup columns: (tid&15) + 16u.
    const int colb = tid & 15;
    const int base_s = (tid * 4) & 63;
    int off[4];
    bool identity = true;
#pragma unroll
    for (int u = 0; u < 4; u++) {
        int s  = base_s + u;                 // < 64, no wrap
        off[u] = u + idx[s] - s;             // input offset vs 4*i4
        identity &= (off[u] == u);
    }

    if (identity) {
        const float4* __restrict__ in4 = reinterpret_cast<const float4*>(in);
        float4* __restrict__ out4      = reinterpret_cast<float4*>(out);
        for (int i4 = tid; i4 < n4; i4 += nthreads) {
            float4 xv = __ldg(in4 + i4);
            float4 r;
            r.x = cubic_lookup(tab, colb,      xv.x);
            r.y = cubic_lookup(tab, colb + 16, xv.y);
            r.z = cubic_lookup(tab, colb + 32, xv.z);
            r.w = cubic_lookup(tab, colb + 48, xv.w);
            out4[i4] = r;
        }
    } else {
        float4* __restrict__ out4 = reinterpret_cast<float4*>(out);
        for (int i4 = tid; i4 < n4; i4 += nthreads) {
            const int b4 = i4 << 2;
            float4 r;
            r.x = cubic_lookup(tab, colb,      __ldg(in + b4 + off[0]));
            r.y = cubic_lookup(tab, colb + 16, __ldg(in + b4 + off[1]));
            r.z = cubic_lookup(tab, colb + 32, __ldg(in + b4 + off[2]));
            r.w = cubic_lookup(tab, colb + 48, __ldg(in + b4 + off[3]));
            out4[i4] = r;
        }
    }
}

extern "C" void kernel_launch(void* const* d_in, const int* in_sizes, int n_in,
                              void* d_out, int out_size)
{
    const float* inputs = (const float*)d_in[0];
    const int*   idx    = (const int*)  d_in[1];
    const float* W1     = (const float*)d_in[2];
    const float* b1     = (const float*)d_in[3];
    const float* W2     = (const float*)d_in[4];
    const float* b2     = (const float*)d_in[5];
    const float* W3     = (const float*)d_in[6];
    const float* b3     = (const float*)d_in[7];
    float*       outp   = (float*)d_out;

    cudaFuncSetAttribute(eval_kernel,
                         cudaFuncAttributeMaxDynamicSharedMemorySize,
                         SMEM_BYTES);

    setup_kernel<<<SUBNETS, 256>>>(W1, b1, W2, b2, W3, b3);

    const int n4 = out_size >> 2;            // 2,097,152
    eval_kernel<<<EVAL_GRID, EVAL_BLOCK, SMEM_BYTES>>>(inputs, idx, outp, n4);
}